// round 17
// baseline (speedup 1.0000x reference)
#include <cuda_runtime.h>

#define N_NODES 10000
#define N_EDGES 640000
#define D 128
#define CAP 160              // per-receiver bucket capacity (max degree ~100)
#define NPB 8                // nodes per fused block (8 warps, 256 threads)

// Scratch (allocation-free rule: __device__ globals).
// g_count starts zero (static init) and is re-zeroed by fused_kernel each run.
__device__ int g_count[N_NODES];          // in-degree (also placement cursor)
__device__ int g_ss[N_NODES * CAP];       // sender ids, bucketed by receiver

// ---------------------------------------------------------------------------
// K1: bucketed CSR build — ONE atomic yields both count and position.
// ---------------------------------------------------------------------------
__global__ void __launch_bounds__(256) place_kernel(
    const int* __restrict__ senders, const int* __restrict__ receivers) {
    int e = blockIdx.x * blockDim.x + threadIdx.x;
    if (e >= N_EDGES) return;
    int r = __ldg(receivers + e);
    int s = __ldg(senders + e);
    int pos = atomicAdd(&g_count[r], 1);
    if (pos < CAP) g_ss[(size_t)r * CAP + pos] = s;
}

// ---------------------------------------------------------------------------
// K2 (fused): gather/accumulate/normalize 8 nodes into smem (unroll-8 MLP,
// the R13 config that measured fastest), then project warp-per-node:
// warp w computes out[node_w] = As[w] @ W + b across all 128 columns.
//   per k: 1 broadcast LDS.32 (As[w][k]) + 1 LDG.128 (W row, L1-resident,
//          reused by all 8 warps) + 4 FFMA.
// No split-k partials, no second __syncthreads, no smem reduce tail.
// g_count[node] is reset after its single read (replaces the zero kernel).
// ---------------------------------------------------------------------------
__global__ void __launch_bounds__(256) fused_kernel(
    const float* __restrict__ nodes,
    const float* __restrict__ W,
    const float* __restrict__ b,
    float* __restrict__ out)
{
    __shared__ float As[NPB][D];        // 4 KB

    int tid  = threadIdx.x;
    int w    = tid >> 5;
    int lane = tid & 31;
    int node = blockIdx.x * NPB + w;

    // ---------------- Phase 1: gather + accumulate + normalize -------------
    {
        int cnt_raw = g_count[node];
        if (lane == 0) g_count[node] = 0;   // reset for next replay (sole reader)
        int cnt = min(cnt_raw, CAP);
        const int* bucket = g_ss + (size_t)node * CAP;

        const float4* nodes4 = reinterpret_cast<const float4*>(nodes);
        float4 acc = make_float4(0.f, 0.f, 0.f, 0.f);

        int i = 0;
        for (; i + 8 <= cnt; i += 8) {
            int s[8];
            #pragma unroll
            for (int k = 0; k < 8; k++) s[k] = __ldg(bucket + i + k);
            float4 v[8];
            #pragma unroll
            for (int k = 0; k < 8; k++) v[k] = __ldg(nodes4 + (size_t)s[k] * 32 + lane);
            #pragma unroll
            for (int k = 0; k < 8; k++) {
                acc.x += v[k].x; acc.y += v[k].y; acc.z += v[k].z; acc.w += v[k].w;
            }
        }
        for (; i < cnt; i++) {
            int s = __ldg(bucket + i);
            float4 v = __ldg(nodes4 + (size_t)s * 32 + lane);
            acc.x += v.x; acc.y += v.y; acc.z += v.z; acc.w += v.w;
        }

        float invd = 1.0f / fmaxf((float)cnt_raw, 1.0f);
        acc.x *= invd; acc.y *= invd; acc.z *= invd; acc.w *= invd;
        reinterpret_cast<float4*>(&As[w][0])[lane] = acc;
    }
    __syncthreads();

    // ---------------- Phase 2: warp-per-node GEMM row -----------------------
    {
        const float4* W4 = reinterpret_cast<const float4*>(W);
        float4 acc = make_float4(0.f, 0.f, 0.f, 0.f);

        #pragma unroll 8
        for (int k = 0; k < D; k++) {
            float a = As[w][k];                      // warp-broadcast LDS
            float4 w4 = __ldg(W4 + k * (D / 4) + lane);
            acc.x += a * w4.x;
            acc.y += a * w4.y;
            acc.z += a * w4.z;
            acc.w += a * w4.w;
        }

        float4 bv = __ldg(reinterpret_cast<const float4*>(b) + lane);
        acc.x += bv.x; acc.y += bv.y; acc.z += bv.z; acc.w += bv.w;
        reinterpret_cast<float4*>(out + (size_t)node * D)[lane] = acc;
    }
}

// ---------------------------------------------------------------------------
// Launch
// ---------------------------------------------------------------------------
extern "C" void kernel_launch(void* const* d_in, const int* in_sizes, int n_in,
                              void* d_out, int out_size) {
    const float* nodes     = (const float*)d_in[0];
    const int*   senders   = (const int*)d_in[1];
    const int*   receivers = (const int*)d_in[2];
    const float* W         = (const float*)d_in[3];
    const float* b         = (const float*)d_in[4];
    float* out = (float*)d_out;

    place_kernel<<<(N_EDGES + 255) / 256, 256>>>(senders, receivers);
    fused_kernel<<<N_NODES / NPB, 256>>>(nodes, W, b, out);
}